// round 8
// baseline (speedup 1.0000x reference)
#include <cuda_runtime.h>

// ---------------- problem constants ----------------
// B=2, C=21, H=W=512, pooled 128x128, K=11 (radius 5), 5 steps, pad=(0,0)

// ---------------- scratch (device globals; no mallocs allowed) ----------------
__device__ float g_unary[11010048];   // [2][21][512][512]
__device__ float g_qb[688128];        // [2][21][128][128]
__device__ float g_msgp[2752512];     // [4 tap-groups][2][21][128][128] partial messages
__device__ float g_kcomb[3964928];    // [2][128y][121j][128x]  (y-major, j inner-contiguous rows)
__device__ float g_rgbp[98304];       // [2][3][128][128]    (already /13)

// ---------------- 4x4 avg-pool of x, folded /13 ----------------
__global__ void k_poolrgb(const float* __restrict__ x) {
  int idx = blockIdx.x * 256 + threadIdx.x;  // over 2*3*128*128
  if (idx >= 98304) return;
  int xp = idx & 127, yp = (idx >> 7) & 127, c = idx >> 14;  // c = b*3+ch
  const float* p = x + ((size_t)c << 18) + ((yp * 4) << 9) + (xp * 4);
  float s = 0.f;
#pragma unroll
  for (int i = 0; i < 4; i++)
#pragma unroll
    for (int j = 0; j < 4; j++) s += p[(i << 9) + j];
  g_rgbp[idx] = s * (1.0f / 208.0f);  // /16 pool, /13 feature scale
}

// ---------------- combined pairwise kernel: w1*bilateral + w2*spatial ----------------
// writes g_kcomb[b][y][j][x]
__global__ void k_kernels(const float* __restrict__ pw) {
  __shared__ float rs[3][18][42];
  __shared__ float sA[121], sS[121];
  const int b  = blockIdx.z;
  const int x0 = blockIdx.x * 32, y0 = blockIdx.y * 8;
  const int tx = threadIdx.x, ty = threadIdx.y;
  const int tid = ty * 32 + tx;
  if (tid < 121) {
    int dy = tid / 11 - 5, dx = tid % 11 - 5;
    float d2 = (float)(dy * dy + dx * dx);
    sA[tid] = __expf(-d2 * (1.0f / 800.0f));  // pooled YX/80: (4d/80)^2/2
    sS[tid] = __expf(-d2 * (8.0f / 9.0f));    // pooled YX/3 : (4d/3)^2/2
  }
  for (int i = tid; i < 3 * 18 * 42; i += 256) {
    int c = i / 756, rem = i % 756, yy = rem / 42, xx = rem % 42;
    int gy = y0 + yy - 5, gx = x0 + xx - 5;
    float v = 0.f;
    if (gy >= 0 && gy < 128 && gx >= 0 && gx < 128)
      v = g_rgbp[((b * 3 + c) << 14) + (gy << 7) + gx];
    rs[c][yy][xx] = v;
  }
  __syncthreads();
  const float w1 = pw[0], w2 = pw[1];
  const float r0 = rs[0][ty + 5][tx + 5];
  const float r1 = rs[1][ty + 5][tx + 5];
  const float r2 = rs[2][ty + 5][tx + 5];
  const int y = y0 + ty, xg = x0 + tx;
  float* outp = g_kcomb + (((size_t)(b * 128 + y) * 121) << 7) + xg;
  for (int dy = 0; dy < 11; dy++) {
    for (int dx = 0; dx < 11; dx++) {
      int j = dy * 11 + dx;
      int ny = y + dy - 5, nx = xg + dx - 5;
      float val = 0.f;  // OOB entries multiply zero-padded Q patches -> store 0
      if (ny >= 0 && ny < 128 && nx >= 0 && nx < 128) {
        float a = rs[0][ty + dy][tx + dx] - r0;
        float bb = rs[1][ty + dy][tx + dx] - r1;
        float cc = rs[2][ty + dy][tx + dx] - r2;
        float d2 = a * a + bb * bb + cc * cc;
        val = fmaf(w1 * sA[j], __expf(-0.5f * d2), w2 * sS[j]);
      }
      outp[j << 7] = val;
    }
  }
}

// ---------------- fused: conv(3->21) -> write unary -> softmax -> 4x4 pool ----------------
// block 32x8, grid (16,64,2)
__global__ void k_convsoft(const float* __restrict__ x, const float* __restrict__ w,
                           const float* __restrict__ bias, const float* __restrict__ uwp) {
  __shared__ float xs[3][10][34];
  __shared__ float ws[567];
  __shared__ float bs[21];
  __shared__ float ps[8][8][21];
  const int b  = blockIdx.z;
  const int x0 = blockIdx.x * 32, y0 = blockIdx.y * 8;
  const int tx = threadIdx.x, ty = threadIdx.y;
  const int tid = ty * 32 + tx;
  const float uw = uwp[0];
  for (int i = tid; i < 567; i += 256) ws[i] = w[i];
  if (tid < 21) bs[tid] = bias[tid];
  for (int i = tid; i < 3 * 10 * 34; i += 256) {
    int c = i / 340, rem = i % 340, yy = rem / 34, xx = rem % 34;
    int gy = y0 + yy - 1, gx = x0 + xx - 1;
    float v = 0.f;
    if (gy >= 0 && gy < 512 && gx >= 0 && gx < 512)
      v = x[((size_t)(b * 3 + c) << 18) + (gy << 9) + gx];
    xs[c][yy][xx] = v;
  }
  __syncthreads();
  float r[27];
#pragma unroll
  for (int c = 0; c < 3; c++)
#pragma unroll
    for (int ky = 0; ky < 3; ky++)
#pragma unroll
      for (int kx = 0; kx < 3; kx++)
        r[c * 9 + ky * 3 + kx] = xs[c][ty + ky][tx + kx];
  float* outp = g_unary + ((size_t)b * 21 << 18) + ((y0 + ty) << 9) + (x0 + tx);
  float logit[21];
  float mx = -1e30f;
#pragma unroll
  for (int o = 0; o < 21; o++) {
    float acc = bs[o];
#pragma unroll
    for (int i = 0; i < 27; i++) acc = fmaf(r[i], ws[o * 27 + i], acc);
    outp[(size_t)o << 18] = acc;
    float v = uw * acc;
    logit[o] = v;
    mx = fmaxf(mx, v);
  }
  float s = 0.f;
#pragma unroll
  for (int c = 0; c < 21; c++) { float e = __expf(logit[c] - mx); logit[c] = e; s += e; }
  float inv = __frcp_rn(s);
#pragma unroll
  for (int c = 0; c < 21; c++) {
    float q = logit[c] * inv;
    q += __shfl_down_sync(0xffffffffu, q, 1);
    q += __shfl_down_sync(0xffffffffu, q, 2);
    logit[c] = q;
  }
  if ((tx & 3) == 0) {
#pragma unroll
    for (int c = 0; c < 21; c++) ps[ty][tx >> 2][c] = logit[c];
  }
  __syncthreads();
  for (int i = tid; i < 336; i += 256) {
    int c = i % 21, pxx = (i / 21) & 7, pyy = i / 168;
    float sum = ps[pyy * 4 + 0][pxx][c] + ps[pyy * 4 + 1][pxx][c] +
                ps[pyy * 4 + 2][pxx][c] + ps[pyy * 4 + 3][pxx][c];
    int yp = (y0 >> 2) + pyy, xp = (x0 >> 2) + pxx;
    g_qb[((b * 21 + c) << 14) + (yp << 7) + xp] = sum * 0.0625f;
  }
}

// ---------------- fused: (uw*unary + upsample(msg)) -> softmax -> 4x4 pool ----------------
__global__ void k_softpool(const float* __restrict__ uwp) {
  __shared__ float ms[21][4][10];
  __shared__ float ps[8][8][21];
  const int b  = blockIdx.z;
  const int x0 = blockIdx.x * 32, y0 = blockIdx.y * 8;
  const int tx = threadIdx.x, ty = threadIdx.y;
  const int tid = ty * 32 + tx;
  const float uw = uwp[0];
  {
    int qx0 = (x0 >> 2) - 1, qy0 = (y0 >> 2) - 1;
    for (int i = tid; i < 21 * 4 * 10; i += 256) {
      int c = i / 40, rem = i % 40, yy = rem / 10, xx = rem % 10;
      int gy = min(max(qy0 + yy, 0), 127), gx = min(max(qx0 + xx, 0), 127);
      size_t idx = (size_t)((b * 21 + c) << 14) + (gy << 7) + gx;
      ms[c][yy][xx] = g_msgp[idx] + g_msgp[688128 + idx] +
                      g_msgp[2 * 688128 + idx] + g_msgp[3 * 688128 + idx];
    }
    __syncthreads();
  }
  const int pxp = tx & 3;
  const int ix0 = (tx >> 2) + (pxp >= 2 ? 1 : 0);
  const float wx0 = (pxp == 0) ? 0.375f : (pxp == 1) ? 0.125f : (pxp == 2) ? 0.875f : 0.625f;
  const float wx1 = 1.f - wx0;
  const int pyp = ty & 3;
  const int iy0 = (ty >> 2) + (pyp >= 2 ? 1 : 0);
  const float wy0 = (pyp == 0) ? 0.375f : (pyp == 1) ? 0.125f : (pyp == 2) ? 0.875f : 0.625f;
  const float wy1 = 1.f - wy0;
  const int y = y0 + ty, xg = x0 + tx;
  const float* up = g_unary + ((size_t)b * 21 << 18) + (y << 9) + xg;
  float logit[21];
  float mx = -1e30f;
#pragma unroll
  for (int c = 0; c < 21; c++) {
    float v = uw * up[(size_t)c << 18];
    float a  = wx0 * ms[c][iy0][ix0]     + wx1 * ms[c][iy0][ix0 + 1];
    float bb = wx0 * ms[c][iy0 + 1][ix0] + wx1 * ms[c][iy0 + 1][ix0 + 1];
    v += wy0 * a + wy1 * bb;
    logit[c] = v;
    mx = fmaxf(mx, v);
  }
  float s = 0.f;
#pragma unroll
  for (int c = 0; c < 21; c++) { float e = __expf(logit[c] - mx); logit[c] = e; s += e; }
  float inv = __frcp_rn(s);
#pragma unroll
  for (int c = 0; c < 21; c++) {
    float q = logit[c] * inv;
    q += __shfl_down_sync(0xffffffffu, q, 1);
    q += __shfl_down_sync(0xffffffffu, q, 2);
    logit[c] = q;
  }
  if ((tx & 3) == 0) {
#pragma unroll
    for (int c = 0; c < 21; c++) ps[ty][tx >> 2][c] = logit[c];
  }
  __syncthreads();
  for (int i = tid; i < 336; i += 256) {
    int c = i % 21, pxx = (i / 21) & 7, pyy = i / 168;
    float sum = ps[pyy * 4 + 0][pxx][c] + ps[pyy * 4 + 1][pxx][c] +
                ps[pyy * 4 + 2][pxx][c] + ps[pyy * 4 + 3][pxx][c];
    int yp = (y0 >> 2) + pyy, xp = (x0 >> 2) + pxx;
    g_qb[((b * 21 + c) << 14) + (yp << 7) + xp] = sum * 0.0625f;
  }
}

// ---------------- pixel-adaptive 11x11 message at 128x128 ----------------
// x4-vectorized; tap-split x4 AND channel-split x2 across blockIdx.z.
// Block (16,4)=64 thr covers 64px x 4 rows x 11 channels; smem 21.1KB;
// __launch_bounds__(64,8): 128-reg cap, ~105 live regs, 7 blocks/SM, 1 wave.
// kcomb layout [b][y][121][x]: the 11 taps of one kernel row are at
// base + dx*512B -> immediate-offset LDG.128, no per-load address ALU.
// grid (2,32,16): z = b*8 + g*2 + cg; tap rows [3g,3g+3) (g=3: [9,11)).
__global__ __launch_bounds__(64, 8) void k_pac() {
  __shared__ float qs[11][6][80];
  const int bz = blockIdx.z;
  const int b  = bz >> 3;
  const int g  = (bz >> 1) & 3;
  const int cg = bz & 1;
  const int s  = g * 3;
  const int nrr = (g == 3) ? 2 : 3;
  const int c0 = cg * 11;             // cg=1 covers c 11..20 (10 real + pad)
  const int x0 = blockIdx.x * 64;
  const int y0 = blockIdx.y * 4;
  const int tx = threadIdx.x;         // 0..15
  const int ty = threadIdx.y;         // 0..3
  const int tid = ty * 16 + tx;
  const int qy0 = y0 - 5 + s;
  for (int i = tid; i < 11 * 6 * 80; i += 64) {
    int c = i / 480, rem = i % 480, r = rem / 80, xx = rem % 80;
    int gy = qy0 + r, gx = x0 - 5 + xx;
    float v = 0.f;
    if (c0 + c < 21 && xx < 74 && gy >= 0 && gy < 128 && gx >= 0 && gx < 128)
      v = g_qb[((b * 21 + c0 + c) << 14) + (gy << 7) + gx];
    qs[c][r][xx] = v;
  }
  __syncthreads();
  const int y  = y0 + ty;
  const int xb = tx * 4;
  float acc[11][4];
#pragma unroll
  for (int c = 0; c < 11; c++)
#pragma unroll
    for (int o = 0; o < 4; o++) acc[c][o] = 0.f;
  for (int rr = s; rr < s + nrr; rr++) {
    const float4* kb = reinterpret_cast<const float4*>(
        g_kcomb + (((size_t)(b * 128 + y) * 121 + rr * 11) << 7) + x0 + xb);
    float4 kv[11];
#pragma unroll
    for (int dx = 0; dx < 11; dx++) kv[dx] = __ldg(kb + (dx << 5));
    const int r = ty + rr - s;   // smem row index
#pragma unroll
    for (int c = 0; c < 11; c++) {
      const float4* qp = reinterpret_cast<const float4*>(&qs[c][r][xb]);
      float4 q0 = qp[0], q1 = qp[1], q2 = qp[2], q3 = qp[3];
      float qf[16] = {q0.x, q0.y, q0.z, q0.w, q1.x, q1.y, q1.z, q1.w,
                      q2.x, q2.y, q2.z, q2.w, q3.x, q3.y, q3.z, q3.w};
#pragma unroll
      for (int dx = 0; dx < 11; dx++) {
        acc[c][0] = fmaf(kv[dx].x, qf[dx + 0], acc[c][0]);
        acc[c][1] = fmaf(kv[dx].y, qf[dx + 1], acc[c][1]);
        acc[c][2] = fmaf(kv[dx].z, qf[dx + 2], acc[c][2]);
        acc[c][3] = fmaf(kv[dx].w, qf[dx + 3], acc[c][3]);
      }
    }
  }
  float* mp = g_msgp + (size_t)g * 688128 + ((size_t)(b * 21 + c0) << 14) + (y << 7) + x0 + xb;
#pragma unroll
  for (int c = 0; c < 11; c++) {
    if (c0 + c < 21) {
      float4 v = make_float4(acc[c][0], acc[c][1], acc[c][2], acc[c][3]);
      *reinterpret_cast<float4*>(mp + ((size_t)c << 14)) = v;
    }
  }
}

// ---------------- last step: logQ = uw*unary + upsample(msg) -> d_out ----------------
__global__ void k_final(const float* __restrict__ uwp, float* __restrict__ out) {
  __shared__ float ms[21][4][10];
  const int b  = blockIdx.z;
  const int x0 = blockIdx.x * 32, y0 = blockIdx.y * 8;
  const int tx = threadIdx.x, ty = threadIdx.y;
  const int tid = ty * 32 + tx;
  const float uw = uwp[0];
  {
    int qx0 = (x0 >> 2) - 1, qy0 = (y0 >> 2) - 1;
    for (int i = tid; i < 21 * 4 * 10; i += 256) {
      int c = i / 40, rem = i % 40, yy = rem / 10, xx = rem % 10;
      int gy = min(max(qy0 + yy, 0), 127), gx = min(max(qx0 + xx, 0), 127);
      size_t idx = (size_t)((b * 21 + c) << 14) + (gy << 7) + gx;
      ms[c][yy][xx] = g_msgp[idx] + g_msgp[688128 + idx] +
                      g_msgp[2 * 688128 + idx] + g_msgp[3 * 688128 + idx];
    }
    __syncthreads();
  }
  const int pxp = tx & 3;
  const int ix0 = (tx >> 2) + (pxp >= 2 ? 1 : 0);
  const float wx0 = (pxp == 0) ? 0.375f : (pxp == 1) ? 0.125f : (pxp == 2) ? 0.875f : 0.625f;
  const float wx1 = 1.f - wx0;
  const int pyp = ty & 3;
  const int iy0 = (ty >> 2) + (pyp >= 2 ? 1 : 0);
  const float wy0 = (pyp == 0) ? 0.375f : (pyp == 1) ? 0.125f : (pyp == 2) ? 0.875f : 0.625f;
  const float wy1 = 1.f - wy0;
  const int y = y0 + ty, xg = x0 + tx;
  const float* up = g_unary + ((size_t)b * 21 << 18) + (y << 9) + xg;
  float* op = out + ((size_t)b * 21 << 18) + (y << 9) + xg;
#pragma unroll
  for (int c = 0; c < 21; c++) {
    float v = uw * up[(size_t)c << 18];
    float a  = wx0 * ms[c][iy0][ix0]     + wx1 * ms[c][iy0][ix0 + 1];
    float bb = wx0 * ms[c][iy0 + 1][ix0] + wx1 * ms[c][iy0 + 1][ix0 + 1];
    op[(size_t)c << 18] = v + wy0 * a + wy1 * bb;
  }
}

extern "C" void kernel_launch(void* const* d_in, const int* in_sizes, int n_in,
                              void* d_out, int out_size) {
  const float* x    = (const float*)d_in[0];
  const float* w    = (const float*)d_in[1];
  const float* bias = (const float*)d_in[2];
  const float* uw   = (const float*)d_in[3];
  const float* pw   = (const float*)d_in[4];
  float* out = (float*)d_out;
  (void)in_sizes; (void)n_in; (void)out_size;

  dim3 b32x8(32, 8);
  k_poolrgb<<<384, 256>>>(x);
  k_kernels<<<dim3(4, 16, 2), b32x8>>>(pw);
  k_convsoft<<<dim3(16, 64, 2), b32x8>>>(x, w, bias, uw);
  for (int t = 0; t < 5; t++) {
    k_pac<<<dim3(2, 32, 16), dim3(16, 4)>>>();
    if (t < 4) k_softpool<<<dim3(16, 64, 2), b32x8>>>(uw);
    else       k_final<<<dim3(16, 64, 2), b32x8>>>(uw, out);
  }
}

// round 9
// speedup vs baseline: 1.1693x; 1.1693x over previous
#include <cuda_runtime.h>

// ---------------- problem constants ----------------
// B=2, C=21, H=W=512, pooled 128x128, K=11 (radius 5), 5 steps, pad=(0,0)

// ---------------- scratch (device globals; no mallocs allowed) ----------------
__device__ float g_unary[11010048];   // [2][21][512][512]
__device__ float g_qb[688128];        // [2][21][128][128]
__device__ float g_msgp[2752512];     // [4 tap-groups][2][21][128][128] partial messages
__device__ float g_kcomb[3964928];    // [2][128y][121j][128x]  (y-major, j inner-contiguous rows)
__device__ float g_rgbp[98304];       // [2][3][128][128]    (already /13)

// ---------------- 4x4 avg-pool of x, folded /13 ----------------
__global__ void k_poolrgb(const float* __restrict__ x) {
  int idx = blockIdx.x * 256 + threadIdx.x;  // over 2*3*128*128
  if (idx >= 98304) return;
  int xp = idx & 127, yp = (idx >> 7) & 127, c = idx >> 14;  // c = b*3+ch
  const float* p = x + ((size_t)c << 18) + ((yp * 4) << 9) + (xp * 4);
  float s = 0.f;
#pragma unroll
  for (int i = 0; i < 4; i++)
#pragma unroll
    for (int j = 0; j < 4; j++) s += p[(i << 9) + j];
  g_rgbp[idx] = s * (1.0f / 208.0f);  // /16 pool, /13 feature scale
}

// ---------------- combined pairwise kernel: w1*bilateral + w2*spatial ----------------
// writes g_kcomb[b][y][j][x]
__global__ void k_kernels(const float* __restrict__ pw) {
  __shared__ float rs[3][18][42];
  __shared__ float sA[121], sS[121];
  const int b  = blockIdx.z;
  const int x0 = blockIdx.x * 32, y0 = blockIdx.y * 8;
  const int tx = threadIdx.x, ty = threadIdx.y;
  const int tid = ty * 32 + tx;
  if (tid < 121) {
    int dy = tid / 11 - 5, dx = tid % 11 - 5;
    float d2 = (float)(dy * dy + dx * dx);
    sA[tid] = __expf(-d2 * (1.0f / 800.0f));  // pooled YX/80: (4d/80)^2/2
    sS[tid] = __expf(-d2 * (8.0f / 9.0f));    // pooled YX/3 : (4d/3)^2/2
  }
  for (int i = tid; i < 3 * 18 * 42; i += 256) {
    int c = i / 756, rem = i % 756, yy = rem / 42, xx = rem % 42;
    int gy = y0 + yy - 5, gx = x0 + xx - 5;
    float v = 0.f;
    if (gy >= 0 && gy < 128 && gx >= 0 && gx < 128)
      v = g_rgbp[((b * 3 + c) << 14) + (gy << 7) + gx];
    rs[c][yy][xx] = v;
  }
  __syncthreads();
  const float w1 = pw[0], w2 = pw[1];
  const float r0 = rs[0][ty + 5][tx + 5];
  const float r1 = rs[1][ty + 5][tx + 5];
  const float r2 = rs[2][ty + 5][tx + 5];
  const int y = y0 + ty, xg = x0 + tx;
  float* outp = g_kcomb + (((size_t)(b * 128 + y) * 121) << 7) + xg;
  for (int dy = 0; dy < 11; dy++) {
    for (int dx = 0; dx < 11; dx++) {
      int j = dy * 11 + dx;
      int ny = y + dy - 5, nx = xg + dx - 5;
      float val = 0.f;  // OOB entries multiply zero-padded Q patches -> store 0
      if (ny >= 0 && ny < 128 && nx >= 0 && nx < 128) {
        float a = rs[0][ty + dy][tx + dx] - r0;
        float bb = rs[1][ty + dy][tx + dx] - r1;
        float cc = rs[2][ty + dy][tx + dx] - r2;
        float d2 = a * a + bb * bb + cc * cc;
        val = fmaf(w1 * sA[j], __expf(-0.5f * d2), w2 * sS[j]);
      }
      outp[j << 7] = val;
    }
  }
}

// ---------------- fused: conv(3->21) -> write unary -> softmax -> 4x4 pool ----------------
// block 32x8, grid (16,64,2)
__global__ void k_convsoft(const float* __restrict__ x, const float* __restrict__ w,
                           const float* __restrict__ bias, const float* __restrict__ uwp) {
  __shared__ float xs[3][10][34];
  __shared__ float ws[567];
  __shared__ float bs[21];
  __shared__ float ps[8][8][21];
  const int b  = blockIdx.z;
  const int x0 = blockIdx.x * 32, y0 = blockIdx.y * 8;
  const int tx = threadIdx.x, ty = threadIdx.y;
  const int tid = ty * 32 + tx;
  const float uw = uwp[0];
  for (int i = tid; i < 567; i += 256) ws[i] = w[i];
  if (tid < 21) bs[tid] = bias[tid];
  for (int i = tid; i < 3 * 10 * 34; i += 256) {
    int c = i / 340, rem = i % 340, yy = rem / 34, xx = rem % 34;
    int gy = y0 + yy - 1, gx = x0 + xx - 1;
    float v = 0.f;
    if (gy >= 0 && gy < 512 && gx >= 0 && gx < 512)
      v = x[((size_t)(b * 3 + c) << 18) + (gy << 9) + gx];
    xs[c][yy][xx] = v;
  }
  __syncthreads();
  float r[27];
#pragma unroll
  for (int c = 0; c < 3; c++)
#pragma unroll
    for (int ky = 0; ky < 3; ky++)
#pragma unroll
      for (int kx = 0; kx < 3; kx++)
        r[c * 9 + ky * 3 + kx] = xs[c][ty + ky][tx + kx];
  float* outp = g_unary + ((size_t)b * 21 << 18) + ((y0 + ty) << 9) + (x0 + tx);
  float logit[21];
  float mx = -1e30f;
#pragma unroll
  for (int o = 0; o < 21; o++) {
    float acc = bs[o];
#pragma unroll
    for (int i = 0; i < 27; i++) acc = fmaf(r[i], ws[o * 27 + i], acc);
    outp[(size_t)o << 18] = acc;
    float v = uw * acc;
    logit[o] = v;
    mx = fmaxf(mx, v);
  }
  float s = 0.f;
#pragma unroll
  for (int c = 0; c < 21; c++) { float e = __expf(logit[c] - mx); logit[c] = e; s += e; }
  float inv = __frcp_rn(s);
#pragma unroll
  for (int c = 0; c < 21; c++) {
    float q = logit[c] * inv;
    q += __shfl_down_sync(0xffffffffu, q, 1);
    q += __shfl_down_sync(0xffffffffu, q, 2);
    logit[c] = q;
  }
  if ((tx & 3) == 0) {
#pragma unroll
    for (int c = 0; c < 21; c++) ps[ty][tx >> 2][c] = logit[c];
  }
  __syncthreads();
  for (int i = tid; i < 336; i += 256) {
    int c = i % 21, pxx = (i / 21) & 7, pyy = i / 168;
    float sum = ps[pyy * 4 + 0][pxx][c] + ps[pyy * 4 + 1][pxx][c] +
                ps[pyy * 4 + 2][pxx][c] + ps[pyy * 4 + 3][pxx][c];
    int yp = (y0 >> 2) + pyy, xp = (x0 >> 2) + pxx;
    g_qb[((b * 21 + c) << 14) + (yp << 7) + xp] = sum * 0.0625f;
  }
}

// ---------------- fused: (uw*unary + upsample(msg)) -> softmax -> 4x4 pool ----------------
__global__ void k_softpool(const float* __restrict__ uwp) {
  __shared__ float ms[21][4][10];
  __shared__ float ps[8][8][21];
  const int b  = blockIdx.z;
  const int x0 = blockIdx.x * 32, y0 = blockIdx.y * 8;
  const int tx = threadIdx.x, ty = threadIdx.y;
  const int tid = ty * 32 + tx;
  const float uw = uwp[0];
  {
    int qx0 = (x0 >> 2) - 1, qy0 = (y0 >> 2) - 1;
    for (int i = tid; i < 21 * 4 * 10; i += 256) {
      int c = i / 40, rem = i % 40, yy = rem / 10, xx = rem % 10;
      int gy = min(max(qy0 + yy, 0), 127), gx = min(max(qx0 + xx, 0), 127);
      size_t idx = (size_t)((b * 21 + c) << 14) + (gy << 7) + gx;
      ms[c][yy][xx] = g_msgp[idx] + g_msgp[688128 + idx] +
                      g_msgp[2 * 688128 + idx] + g_msgp[3 * 688128 + idx];
    }
    __syncthreads();
  }
  const int pxp = tx & 3;
  const int ix0 = (tx >> 2) + (pxp >= 2 ? 1 : 0);
  const float wx0 = (pxp == 0) ? 0.375f : (pxp == 1) ? 0.125f : (pxp == 2) ? 0.875f : 0.625f;
  const float wx1 = 1.f - wx0;
  const int pyp = ty & 3;
  const int iy0 = (ty >> 2) + (pyp >= 2 ? 1 : 0);
  const float wy0 = (pyp == 0) ? 0.375f : (pyp == 1) ? 0.125f : (pyp == 2) ? 0.875f : 0.625f;
  const float wy1 = 1.f - wy0;
  const int y = y0 + ty, xg = x0 + tx;
  const float* up = g_unary + ((size_t)b * 21 << 18) + (y << 9) + xg;
  float logit[21];
  float mx = -1e30f;
#pragma unroll
  for (int c = 0; c < 21; c++) {
    float v = uw * up[(size_t)c << 18];
    float a  = wx0 * ms[c][iy0][ix0]     + wx1 * ms[c][iy0][ix0 + 1];
    float bb = wx0 * ms[c][iy0 + 1][ix0] + wx1 * ms[c][iy0 + 1][ix0 + 1];
    v += wy0 * a + wy1 * bb;
    logit[c] = v;
    mx = fmaxf(mx, v);
  }
  float s = 0.f;
#pragma unroll
  for (int c = 0; c < 21; c++) { float e = __expf(logit[c] - mx); logit[c] = e; s += e; }
  float inv = __frcp_rn(s);
#pragma unroll
  for (int c = 0; c < 21; c++) {
    float q = logit[c] * inv;
    q += __shfl_down_sync(0xffffffffu, q, 1);
    q += __shfl_down_sync(0xffffffffu, q, 2);
    logit[c] = q;
  }
  if ((tx & 3) == 0) {
#pragma unroll
    for (int c = 0; c < 21; c++) ps[ty][tx >> 2][c] = logit[c];
  }
  __syncthreads();
  for (int i = tid; i < 336; i += 256) {
    int c = i % 21, pxx = (i / 21) & 7, pyy = i / 168;
    float sum = ps[pyy * 4 + 0][pxx][c] + ps[pyy * 4 + 1][pxx][c] +
                ps[pyy * 4 + 2][pxx][c] + ps[pyy * 4 + 3][pxx][c];
    int yp = (y0 >> 2) + pyy, xp = (x0 >> 2) + pxx;
    g_qb[((b * 21 + c) << 14) + (yp << 7) + xp] = sum * 0.0625f;
  }
}

// ---------------- pixel-adaptive 11x11 message at 128x128 ----------------
// x4-vectorized; tap-split x4 AND channel-split x2 across blockIdx.z.
// Block (16,4)=64 thr covers 64px x 4 rows x 11 channels; smem 21.1KB.
// Fill loop uses pow2 virtual indexing (no int div). Inner dx loop split
// into halves (0..5 / 6..10) so live kv regs drop 44->24 (no spills).
// kcomb layout [b][y][121][x]: taps at base + dx*512B -> immediate LDG.128.
// grid (2,32,16): z = b*8 + g*2 + cg; tap rows [3g,3g+3) (g=3: [9,11)).
__global__ __launch_bounds__(64, 8) void k_pac() {
  __shared__ float qs[11][6][80];
  const int bz = blockIdx.z;
  const int b  = bz >> 3;
  const int g  = (bz >> 1) & 3;
  const int cg = bz & 1;
  const int s  = g * 3;
  const int nrr = (g == 3) ? 2 : 3;
  const int c0 = cg * 11;             // cg=1 covers c 11..20 (10 real + pad)
  const int x0 = blockIdx.x * 64;
  const int y0 = blockIdx.y * 4;
  const int tx = threadIdx.x;         // 0..15
  const int ty = threadIdx.y;         // 0..3
  const int tid = ty * 16 + tx;
  const int qy0 = y0 - 5 + s;
  // zero-fill smem (flat float4, no index math)
  {
    float4 z4 = make_float4(0.f, 0.f, 0.f, 0.f);
    float4* qsf = reinterpret_cast<float4*>(&qs[0][0][0]);
    for (int i = tid; i < 1320; i += 64) qsf[i] = z4;
  }
  __syncthreads();
  // fill valid region; virtual row width 128 -> shift/mask indexing only
  {
    const int cmax = cg ? 10 : 11;
    for (int i = tid; i < 768; i += 64) {
      int r = i >> 7, xx = i & 127;
      int gy = qy0 + r, gx = x0 - 5 + xx;
      if (xx < 74 && gy >= 0 && gy < 128 && gx >= 0 && gx < 128) {
        const float* src = g_qb + ((b * 21 + c0) << 14) + (gy << 7) + gx;
        float* dst = &qs[0][r][xx];
        for (int c = 0; c < cmax; c++) dst[c * 480] = src[(size_t)c << 14];
      }
    }
  }
  __syncthreads();
  const int y  = y0 + ty;
  const int xb = tx * 4;
  float acc[11][4];
#pragma unroll
  for (int c = 0; c < 11; c++)
#pragma unroll
    for (int o = 0; o < 4; o++) acc[c][o] = 0.f;
  for (int rr = s; rr < s + nrr; rr++) {
    const float4* kb = reinterpret_cast<const float4*>(
        g_kcomb + (((size_t)(b * 128 + y) * 121 + rr * 11) << 7) + x0 + xb);
    const int r = ty + rr - s;   // smem row index
    // ---- half A: dx 0..5 (needs q floats 0..8) ----
    {
      float4 kv[6];
#pragma unroll
      for (int dx = 0; dx < 6; dx++) kv[dx] = __ldg(kb + (dx << 5));
#pragma unroll
      for (int c = 0; c < 11; c++) {
        const float4* qp = reinterpret_cast<const float4*>(&qs[c][r][xb]);
        float4 q0 = qp[0], q1 = qp[1], q2 = qp[2];
        float qf[12] = {q0.x, q0.y, q0.z, q0.w, q1.x, q1.y, q1.z, q1.w,
                        q2.x, q2.y, q2.z, q2.w};
#pragma unroll
        for (int dx = 0; dx < 6; dx++) {
          acc[c][0] = fmaf(kv[dx].x, qf[dx + 0], acc[c][0]);
          acc[c][1] = fmaf(kv[dx].y, qf[dx + 1], acc[c][1]);
          acc[c][2] = fmaf(kv[dx].z, qf[dx + 2], acc[c][2]);
          acc[c][3] = fmaf(kv[dx].w, qf[dx + 3], acc[c][3]);
        }
      }
    }
    // ---- half B: dx 6..10 (needs q floats 6..13 -> qf covers 4..15) ----
    {
      float4 kv[5];
#pragma unroll
      for (int dx = 0; dx < 5; dx++) kv[dx] = __ldg(kb + ((dx + 6) << 5));
#pragma unroll
      for (int c = 0; c < 11; c++) {
        const float4* qp = reinterpret_cast<const float4*>(&qs[c][r][xb]);
        float4 q1 = qp[1], q2 = qp[2], q3 = qp[3];
        float qf[12] = {q1.x, q1.y, q1.z, q1.w, q2.x, q2.y, q2.z, q2.w,
                        q3.x, q3.y, q3.z, q3.w};  // qf[k] = q float 4+k
#pragma unroll
        for (int dx = 0; dx < 5; dx++) {
          acc[c][0] = fmaf(kv[dx].x, qf[dx + 2], acc[c][0]);
          acc[c][1] = fmaf(kv[dx].y, qf[dx + 3], acc[c][1]);
          acc[c][2] = fmaf(kv[dx].z, qf[dx + 4], acc[c][2]);
          acc[c][3] = fmaf(kv[dx].w, qf[dx + 5], acc[c][3]);
        }
      }
    }
  }
  float* mp = g_msgp + (size_t)g * 688128 + ((size_t)(b * 21 + c0) << 14) + (y << 7) + x0 + xb;
#pragma unroll
  for (int c = 0; c < 11; c++) {
    if (c0 + c < 21) {
      float4 v = make_float4(acc[c][0], acc[c][1], acc[c][2], acc[c][3]);
      *reinterpret_cast<float4*>(mp + ((size_t)c << 14)) = v;
    }
  }
}

// ---------------- last step: logQ = uw*unary + upsample(msg) -> d_out ----------------
__global__ void k_final(const float* __restrict__ uwp, float* __restrict__ out) {
  __shared__ float ms[21][4][10];
  const int b  = blockIdx.z;
  const int x0 = blockIdx.x * 32, y0 = blockIdx.y * 8;
  const int tx = threadIdx.x, ty = threadIdx.y;
  const int tid = ty * 32 + tx;
  const float uw = uwp[0];
  {
    int qx0 = (x0 >> 2) - 1, qy0 = (y0 >> 2) - 1;
    for (int i = tid; i < 21 * 4 * 10; i += 256) {
      int c = i / 40, rem = i % 40, yy = rem / 10, xx = rem % 10;
      int gy = min(max(qy0 + yy, 0), 127), gx = min(max(qx0 + xx, 0), 127);
      size_t idx = (size_t)((b * 21 + c) << 14) + (gy << 7) + gx;
      ms[c][yy][xx] = g_msgp[idx] + g_msgp[688128 + idx] +
                      g_msgp[2 * 688128 + idx] + g_msgp[3 * 688128 + idx];
    }
    __syncthreads();
  }
  const int pxp = tx & 3;
  const int ix0 = (tx >> 2) + (pxp >= 2 ? 1 : 0);
  const float wx0 = (pxp == 0) ? 0.375f : (pxp == 1) ? 0.125f : (pxp == 2) ? 0.875f : 0.625f;
  const float wx1 = 1.f - wx0;
  const int pyp = ty & 3;
  const int iy0 = (ty >> 2) + (pyp >= 2 ? 1 : 0);
  const float wy0 = (pyp == 0) ? 0.375f : (pyp == 1) ? 0.125f : (pyp == 2) ? 0.875f : 0.625f;
  const float wy1 = 1.f - wy0;
  const int y = y0 + ty, xg = x0 + tx;
  const float* up = g_unary + ((size_t)b * 21 << 18) + (y << 9) + xg;
  float* op = out + ((size_t)b * 21 << 18) + (y << 9) + xg;
#pragma unroll
  for (int c = 0; c < 21; c++) {
    float v = uw * up[(size_t)c << 18];
    float a  = wx0 * ms[c][iy0][ix0]     + wx1 * ms[c][iy0][ix0 + 1];
    float bb = wx0 * ms[c][iy0 + 1][ix0] + wx1 * ms[c][iy0 + 1][ix0 + 1];
    op[(size_t)c << 18] = v + wy0 * a + wy1 * bb;
  }
}

extern "C" void kernel_launch(void* const* d_in, const int* in_sizes, int n_in,
                              void* d_out, int out_size) {
  const float* x    = (const float*)d_in[0];
  const float* w    = (const float*)d_in[1];
  const float* bias = (const float*)d_in[2];
  const float* uw   = (const float*)d_in[3];
  const float* pw   = (const float*)d_in[4];
  float* out = (float*)d_out;
  (void)in_sizes; (void)n_in; (void)out_size;

  dim3 b32x8(32, 8);
  k_poolrgb<<<384, 256>>>(x);
  k_kernels<<<dim3(4, 16, 2), b32x8>>>(pw);
  k_convsoft<<<dim3(16, 64, 2), b32x8>>>(x, w, bias, uw);
  for (int t = 0; t < 5; t++) {
    k_pac<<<dim3(2, 32, 16), dim3(16, 4)>>>();
    if (t < 4) k_softpool<<<dim3(16, 64, 2), b32x8>>>(uw);
    else       k_final<<<dim3(16, 64, 2), b32x8>>>(uw, out);
  }
}